// round 3
// baseline (speedup 1.0000x reference)
#include <cuda_runtime.h>
#include <math.h>
#include <float.h>

#define N_TOK 32768   // B*T
#define DC    256
#define DIN   512
#define NQCB  8
#define NBINS 1024

// -------- scratch (device globals: allocation-free) --------
__device__ float g_h[(size_t)N_TOK * DC];     // tanh projection (later overwritten with quantized)
__device__ float g_res[(size_t)N_TOK * DC];   // running residual
__device__ float g_e2[NQCB * NBINS];          // per-bin squared norms (XLA reduce order)
__device__ float g_commit;                    // commit sum-of-squares accumulator

__global__ void init_kernel() { g_commit = 0.f; }

// XLA/Eigen float tanh rational approximation (bit-matching the reference's tanh)
__device__ __forceinline__ float tanh_ref(float x) {
    const float kClamp = 7.90531110763549805f;
    float xc = fminf(fmaxf(x, -kClamp), kClamp);
    const float a1  = 4.89352455891786e-03f, a3 = 6.37261928875436e-04f,
                a5  = 1.48572235717979e-05f, a7 = 5.12229709037114e-08f,
                a9  = -8.60467152213735e-11f, a11 = 2.00018790482477e-13f,
                a13 = -2.76076847742355e-16f;
    const float b0 = 4.89352518554385e-03f, b2 = 2.26843463243900e-03f,
                b4 = 1.18534705686654e-04f, b6 = 1.19825839466702e-06f;
    float x2 = __fmul_rn(xc, xc);
    float p = fmaf(x2, a13, a11);
    p = fmaf(x2, p, a9);
    p = fmaf(x2, p, a7);
    p = fmaf(x2, p, a5);
    p = fmaf(x2, p, a3);
    p = fmaf(x2, p, a1);
    p = __fmul_rn(xc, p);
    float q = fmaf(x2, b6, b4);
    q = fmaf(x2, q, b2);
    q = fmaf(x2, q, b0);
    float r = __fdiv_rn(p, q);
    return (fabsf(x) < 0.0004f) ? x : r;
}

// ||e||^2 per codebook row, XLA row-reduce order:
// lane sums elements lane, lane+32, ... (ascending), add(mul) no fma, then shuffle tree 16..1.
__global__ void e2_kernel(const float* __restrict__ cb) {
    int gw   = (blockIdx.x * blockDim.x + threadIdx.x) >> 5;
    int lane = threadIdx.x & 31;
    if (gw >= NQCB * NBINS) return;
    const float* row = cb + (size_t)gw * DC;
    float s = 0.f;
    #pragma unroll
    for (int j = 0; j < DC / 32; ++j) {
        float v = row[lane + j * 32];
        s = __fadd_rn(s, __fmul_rn(v, v));
    }
    #pragma unroll
    for (int off = 16; off; off >>= 1)
        s = __fadd_rn(s, __shfl_down_sync(0xffffffffu, s, off));
    if (lane == 0) g_e2[gw] = s;
}

// ---------------------------------------------------------------------------
// 64x64 tile fp32 MMA core: strictly sequential-k, single fp32 accumulator per
// output element (bit-matches cuBLAS SGEMM accumulation).
// ---------------------------------------------------------------------------
template<int KTOT>
__device__ __forceinline__ void mma64(const float* __restrict__ A, int lda,
                                      const float* __restrict__ B, int ldb,
                                      float (&acc)[4][4],
                                      float (*As)[68], float (*Bs)[68])
{
    const int tid = threadIdx.x;
    const int row = tid >> 2;          // 0..63
    const int kq  = (tid & 3) * 4;     // 0,4,8,12
    const int tx  = tid & 15;
    const int ty  = tid >> 4;
    #pragma unroll 1
    for (int kt = 0; kt < KTOT; kt += 16) {
        float4 av = *(const float4*)(A + (size_t)row * lda + kt + kq);
        float4 bv = *(const float4*)(B + (size_t)row * ldb + kt + kq);
        __syncthreads();
        As[kq + 0][row] = av.x; As[kq + 1][row] = av.y; As[kq + 2][row] = av.z; As[kq + 3][row] = av.w;
        Bs[kq + 0][row] = bv.x; Bs[kq + 1][row] = bv.y; Bs[kq + 2][row] = bv.z; Bs[kq + 3][row] = bv.w;
        __syncthreads();
        #pragma unroll
        for (int k = 0; k < 16; ++k) {
            float4 a = *(const float4*)&As[k][ty * 4];
            float4 b = *(const float4*)&Bs[k][tx * 4];
            float ar[4] = {a.x, a.y, a.z, a.w};
            float br[4] = {b.x, b.y, b.z, b.w};
            #pragma unroll
            for (int i = 0; i < 4; ++i)
                #pragma unroll
                for (int j = 0; j < 4; ++j)
                    acc[i][j] = fmaf(ar[i], br[j], acc[i][j]);
        }
    }
}

// -------- GEMM 1: h = tanh_ref(x @ in_w^T + in_b), writes g_h and g_res ----
__global__ void __launch_bounds__(256) gemm_in_kernel(const float* __restrict__ x,
                                                      const float* __restrict__ w,
                                                      const float* __restrict__ b)
{
    __shared__ __align__(16) float As[16][68];
    __shared__ __align__(16) float Bs[16][68];
    const int mBase = blockIdx.y * 64;
    const int nBase = blockIdx.x * 64;
    float acc[4][4] = {};
    mma64<DIN>(x + (size_t)mBase * DIN, DIN, w + (size_t)nBase * DIN, DIN, acc, As, Bs);
    const int tx = threadIdx.x & 15, ty = threadIdx.x >> 4;
    #pragma unroll
    for (int i = 0; i < 4; ++i) {
        int m = mBase + ty * 4 + i;
        #pragma unroll
        for (int j = 0; j < 4; ++j) {
            int n = nBase + tx * 4 + j;
            float v = tanh_ref(__fadd_rn(acc[i][j], b[n]));   // CODEC_RANGE == 1.0
            g_h  [(size_t)m * DC + n] = v;
            g_res[(size_t)m * DC + n] = v;
        }
    }
}

// -------- per-step: r2 + distances (reference rounding) + argmin +
//          residual update + commit. One block = 64 tokens, all 1024 bins. ---
__global__ void __launch_bounds__(256) quant_kernel(const float* __restrict__ cbt,
                                                    int t, float* __restrict__ idx_out)
{
    __shared__ __align__(16) float As[16][68];
    __shared__ __align__(16) float Bs[16][68];
    __shared__ float r2s[64];
    __shared__ float best_val[64];
    __shared__ int   best_idx[64];
    __shared__ float warp_sum[8];
    const int tid   = threadIdx.x;
    const int mBase = blockIdx.x * 64;
    const int tx = tid & 15, ty = tid >> 4;
    const int lane = tid & 31, wrp = tid >> 5;

    // r2 per token, XLA row-reduce order (stride-32 ascending + shuffle tree)
    #pragma unroll 1
    for (int u = 0; u < 8; ++u) {
        int tok = wrp * 8 + u;
        const float* row = g_res + (size_t)(mBase + tok) * DC;
        float s = 0.f;
        #pragma unroll
        for (int j = 0; j < DC / 32; ++j) {
            float v = row[lane + j * 32];
            s = __fadd_rn(s, __fmul_rn(v, v));
        }
        #pragma unroll
        for (int off = 16; off; off >>= 1)
            s = __fadd_rn(s, __shfl_down_sync(0xffffffffu, s, off));
        if (lane == 0) r2s[tok] = s;
    }
    if (tid < 64) { best_val[tid] = FLT_MAX; best_idx[tid] = 0; }
    // ordering vs reads below guaranteed by syncthreads inside mma64

    #pragma unroll 1
    for (int nb = 0; nb < 16; ++nb) {
        float acc[4][4] = {};
        mma64<DC>(g_res + (size_t)mBase * DC, DC,
                  cbt + (size_t)(nb * 64) * DC, DC, acc, As, Bs);
        float4 e2v = *(const float4*)&g_e2[t * NBINS + nb * 64 + tx * 4];
        float e2r[4] = {e2v.x, e2v.y, e2v.z, e2v.w};
        int binBase = nb * 64 + tx * 4;
        #pragma unroll
        for (int i = 0; i < 4; ++i) {
            float r2 = r2s[ty * 4 + i];
            float bv = FLT_MAX; int bi = 0;
            #pragma unroll
            for (int j = 0; j < 4; ++j) {
                // reference rounding: fl(fl(r2 - 2*dot) + e2); 2*dot is exact.
                float s = __fadd_rn(__fsub_rn(r2, __fmul_rn(2.0f, acc[i][j])), e2r[j]);
                if (s < bv) { bv = s; bi = binBase + j; }   // ascending j: lower idx wins ties
            }
            #pragma unroll
            for (int off = 8; off; off >>= 1) {
                float v2 = __shfl_down_sync(0xffffffffu, bv, off, 16);
                int   i2 = __shfl_down_sync(0xffffffffu, bi, off, 16);
                if (v2 < bv || (v2 == bv && i2 < bi)) { bv = v2; bi = i2; }
            }
            if (tx == 0) {
                int tok = ty * 4 + i;
                if (bv < best_val[tok]) { best_val[tok] = bv; best_idx[tok] = bi; }
            }
        }
    }
    __syncthreads();

    // residual -= codebook[idx]; commit += ||new residual||^2 ; write idx
    const int tok = tid >> 2;            // 4 threads per token
    const int seg = tid & 3;             // 64 dims each
    const int m   = mBase + tok;
    const int bi  = best_idx[tok];
    const float4* e4 = (const float4*)(cbt + (size_t)bi * DC) + seg * 16;
    float4*       r4 = (float4*)(g_res + (size_t)m * DC) + seg * 16;
    float ss = 0.f;
    #pragma unroll
    for (int u = 0; u < 16; ++u) {
        float4 r = r4[u], e = e4[u];
        r.x = __fsub_rn(r.x, e.x); r.y = __fsub_rn(r.y, e.y);
        r.z = __fsub_rn(r.z, e.z); r.w = __fsub_rn(r.w, e.w);
        r4[u] = r;
        ss = fmaf(r.x, r.x, fmaf(r.y, r.y, fmaf(r.z, r.z, fmaf(r.w, r.w, ss))));
    }
    if (seg == 0) idx_out[m] = (float)bi;
    #pragma unroll
    for (int off = 16; off; off >>= 1) ss += __shfl_down_sync(0xffffffffu, ss, off);
    if ((tid & 31) == 0) warp_sum[tid >> 5] = ss;
    __syncthreads();
    if (tid == 0) {
        float s = 0.f;
        #pragma unroll
        for (int w = 0; w < 8; ++w) s += warp_sum[w];
        atomicAdd(&g_commit, s);
    }
}

// -------- quantized = h - residual_final (overwrite g_h) -------------------
__global__ void qsum_kernel() {
    size_t i = (size_t)blockIdx.x * blockDim.x + threadIdx.x;
    float4* h4 = (float4*)g_h;
    const float4* r4 = (const float4*)g_res;
    float4 h = h4[i], r = r4[i];
    h.x = __fsub_rn(h.x, r.x); h.y = __fsub_rn(h.y, r.y);
    h.z = __fsub_rn(h.z, r.z); h.w = __fsub_rn(h.w, r.w);
    h4[i] = h;
}

// -------- GEMM 2: out = quantized @ out_w^T + out_b ------------------------
__global__ void __launch_bounds__(256) gemm_out_kernel(const float* __restrict__ w,
                                                       const float* __restrict__ b,
                                                       float* __restrict__ outp)
{
    __shared__ __align__(16) float As[16][68];
    __shared__ __align__(16) float Bs[16][68];
    const int mBase = blockIdx.y * 64;
    const int nBase = blockIdx.x * 64;
    float acc[4][4] = {};
    mma64<DC>(g_h + (size_t)mBase * DC, DC, w + (size_t)nBase * DC, DC, acc, As, Bs);
    const int tx = threadIdx.x & 15, ty = threadIdx.x >> 4;
    #pragma unroll
    for (int i = 0; i < 4; ++i) {
        int m = mBase + ty * 4 + i;
        #pragma unroll
        for (int j = 0; j < 4; ++j) {
            int n = nBase + tx * 4 + j;
            outp[(size_t)m * DIN + n] = __fadd_rn(acc[i][j], b[n]);
        }
    }
}

__global__ void fin_kernel(float* __restrict__ loss) {
    // commit_loss = 0.1 * sum_t mean(r_new_t^2);  mean denom = 8*4096*256
    *loss = 0.1f * g_commit * (1.0f / 8388608.0f);
}

extern "C" void kernel_launch(void* const* d_in, const int* in_sizes, int n_in,
                              void* d_out, int out_size)
{
    const float* x     = (const float*)d_in[0];
    const float* in_w  = (const float*)d_in[1];
    const float* in_b  = (const float*)d_in[2];
    const float* out_w = (const float*)d_in[3];
    const float* out_b = (const float*)d_in[4];
    const float* cb    = (const float*)d_in[5];

    float* outp     = (float*)d_out;                       // [32768, 512]
    float* idx_out  = outp + (size_t)N_TOK * DIN;          // [8, 32768]
    float* loss_out = outp + (size_t)out_size - 1;         // scalar

    init_kernel<<<1, 1>>>();
    e2_kernel<<<(NQCB * NBINS * 32) / 256, 256>>>(cb);
    gemm_in_kernel<<<dim3(DC / 64, N_TOK / 64), 256>>>(x, in_w, in_b);
    for (int t = 0; t < NQCB; ++t)
        quant_kernel<<<N_TOK / 64, 256>>>(cb + (size_t)t * NBINS * DC, t,
                                          idx_out + (size_t)t * N_TOK);
    qsum_kernel<<<(N_TOK * DC / 4) / 256, 256>>>();
    gemm_out_kernel<<<dim3(DIN / 64, N_TOK / 64), 256>>>(out_w, out_b, outp);
    fin_kernel<<<1, 1>>>(loss_out);
}

// round 4
// speedup vs baseline: 1.2156x; 1.2156x over previous
#include <cuda_runtime.h>
#include <math.h>
#include <float.h>

#define N_TOK 32768   // B*T
#define DC    256
#define DIN   512
#define NQCB  8
#define NBINS 1024

// -------- scratch (device globals: allocation-free) --------
__device__ float g_h[(size_t)N_TOK * DC];     // tanh projection (later overwritten with quantized)
__device__ float g_res[(size_t)N_TOK * DC];   // running residual
__device__ float g_e2[NQCB * NBINS];          // per-bin squared norms (XLA reduce order)
__device__ float g_commit;                    // commit sum-of-squares accumulator

__global__ void init_kernel() { g_commit = 0.f; }

// XLA/Eigen float tanh rational approximation (bit-matching the reference's tanh)
__device__ __forceinline__ float tanh_ref(float x) {
    const float kClamp = 7.90531110763549805f;
    float xc = fminf(fmaxf(x, -kClamp), kClamp);
    const float a1  = 4.89352455891786e-03f, a3 = 6.37261928875436e-04f,
                a5  = 1.48572235717979e-05f, a7 = 5.12229709037114e-08f,
                a9  = -8.60467152213735e-11f, a11 = 2.00018790482477e-13f,
                a13 = -2.76076847742355e-16f;
    const float b0 = 4.89352518554385e-03f, b2 = 2.26843463243900e-03f,
                b4 = 1.18534705686654e-04f, b6 = 1.19825839466702e-06f;
    float x2 = __fmul_rn(xc, xc);
    float p = fmaf(x2, a13, a11);
    p = fmaf(x2, p, a9);
    p = fmaf(x2, p, a7);
    p = fmaf(x2, p, a5);
    p = fmaf(x2, p, a3);
    p = fmaf(x2, p, a1);
    p = __fmul_rn(xc, p);
    float q = fmaf(x2, b6, b4);
    q = fmaf(x2, q, b2);
    q = fmaf(x2, q, b0);
    float r = __fdiv_rn(p, q);
    return (fabsf(x) < 0.0004f) ? x : r;
}

// ||e||^2 per codebook row, XLA row-reduce order
__global__ void e2_kernel(const float* __restrict__ cb) {
    int gw   = (blockIdx.x * blockDim.x + threadIdx.x) >> 5;
    int lane = threadIdx.x & 31;
    if (gw >= NQCB * NBINS) return;
    const float* row = cb + (size_t)gw * DC;
    float s = 0.f;
    #pragma unroll
    for (int j = 0; j < DC / 32; ++j) {
        float v = row[lane + j * 32];
        s = __fadd_rn(s, __fmul_rn(v, v));
    }
    #pragma unroll
    for (int off = 16; off; off >>= 1)
        s = __fadd_rn(s, __shfl_down_sync(0xffffffffu, s, off));
    if (lane == 0) g_e2[gw] = s;
}

// ---------------------------------------------------------------------------
// 128x128 tile fp32 core: C += A[128,KTOT] * B[128,KTOT]^T.
// 256 threads (16x16), 8x8 per-thread accumulators as 2x2 grid of 4x4 tiles.
// Strictly sequential-k single-accumulator per output (bit-stable argmin).
// Register prefetch of next k-chunk overlaps global latency with FMA work.
// ---------------------------------------------------------------------------
template<int KTOT>
__device__ __forceinline__ void mma128(const float* __restrict__ A,
                                       const float* __restrict__ B,
                                       int lda, int ldb,
                                       float (&acc)[8][8],
                                       float (*As)[132], float (*Bs)[132])
{
    const int tid = threadIdx.x;
    const int row = tid >> 1;          // 0..127
    const int kq  = (tid & 1) * 8;     // 0 or 8
    const int tx  = tid & 15;
    const int ty  = tid >> 4;

    float4 pa0 = *(const float4*)(A + (size_t)row * lda + kq);
    float4 pa1 = *(const float4*)(A + (size_t)row * lda + kq + 4);
    float4 pb0 = *(const float4*)(B + (size_t)row * ldb + kq);
    float4 pb1 = *(const float4*)(B + (size_t)row * ldb + kq + 4);

    #pragma unroll 1
    for (int kt = 0; kt < KTOT; kt += 16) {
        __syncthreads();   // previous compute (or caller smem init) done
        As[kq + 0][row] = pa0.x; As[kq + 1][row] = pa0.y; As[kq + 2][row] = pa0.z; As[kq + 3][row] = pa0.w;
        As[kq + 4][row] = pa1.x; As[kq + 5][row] = pa1.y; As[kq + 6][row] = pa1.z; As[kq + 7][row] = pa1.w;
        Bs[kq + 0][row] = pb0.x; Bs[kq + 1][row] = pb0.y; Bs[kq + 2][row] = pb0.z; Bs[kq + 3][row] = pb0.w;
        Bs[kq + 4][row] = pb1.x; Bs[kq + 5][row] = pb1.y; Bs[kq + 6][row] = pb1.z; Bs[kq + 7][row] = pb1.w;
        __syncthreads();
        if (kt + 16 < KTOT) {
            pa0 = *(const float4*)(A + (size_t)row * lda + kt + 16 + kq);
            pa1 = *(const float4*)(A + (size_t)row * lda + kt + 16 + kq + 4);
            pb0 = *(const float4*)(B + (size_t)row * ldb + kt + 16 + kq);
            pb1 = *(const float4*)(B + (size_t)row * ldb + kt + 16 + kq + 4);
        }
        #pragma unroll
        for (int k = 0; k < 16; ++k) {
            float4 a0 = *(const float4*)&As[k][ty * 4];
            float4 a1 = *(const float4*)&As[k][64 + ty * 4];
            float4 b0 = *(const float4*)&Bs[k][tx * 4];
            float4 b1 = *(const float4*)&Bs[k][64 + tx * 4];
            float ar[8] = {a0.x, a0.y, a0.z, a0.w, a1.x, a1.y, a1.z, a1.w};
            float br[8] = {b0.x, b0.y, b0.z, b0.w, b1.x, b1.y, b1.z, b1.w};
            #pragma unroll
            for (int i = 0; i < 8; ++i)
                #pragma unroll
                for (int j = 0; j < 8; ++j)
                    acc[i][j] = fmaf(ar[i], br[j], acc[i][j]);
        }
    }
}

// row/col mapping for the 2x2-of-4x4 layout
__device__ __forceinline__ int map8(int base4, int i) {   // i 0..7
    return (i < 4) ? base4 + i : 64 + base4 + (i - 4);
}

// -------- GEMM 1: h = tanh_ref(x @ in_w^T + in_b), writes g_h and g_res ----
__global__ void __launch_bounds__(256, 2) gemm_in_kernel(const float* __restrict__ x,
                                                         const float* __restrict__ w,
                                                         const float* __restrict__ b)
{
    __shared__ __align__(16) float As[16][132];
    __shared__ __align__(16) float Bs[16][132];
    const int mBase = blockIdx.y * 128;
    const int nBase = blockIdx.x * 128;
    float acc[8][8] = {};
    mma128<DIN>(x + (size_t)mBase * DIN, w + (size_t)nBase * DIN, DIN, DIN, acc, As, Bs);
    const int tx = threadIdx.x & 15, ty = threadIdx.x >> 4;
    #pragma unroll
    for (int i = 0; i < 8; ++i) {
        int m = mBase + map8(ty * 4, i);
        #pragma unroll
        for (int j = 0; j < 8; ++j) {
            int n = nBase + map8(tx * 4, j);
            float v = tanh_ref(__fadd_rn(acc[i][j], b[n]));   // CODEC_RANGE == 1.0
            g_h  [(size_t)m * DC + n] = v;
            g_res[(size_t)m * DC + n] = v;
        }
    }
}

// -------- per-step: r2 + distances (reference rounding) + argmin +
//          residual update + commit. One block = 128 tokens, all 1024 bins. --
__global__ void __launch_bounds__(256, 2) quant_kernel(const float* __restrict__ cbt,
                                                       int t, float* __restrict__ idx_out)
{
    __shared__ __align__(16) float As[16][132];
    __shared__ __align__(16) float Bs[16][132];
    __shared__ float r2s[128];
    __shared__ float best_val[128];
    __shared__ int   best_idx[128];
    __shared__ float warp_sum[8];
    const int tid   = threadIdx.x;
    const int mBase = blockIdx.x * 128;
    const int tx = tid & 15, ty = tid >> 4;
    const int lane = tid & 31, wrp = tid >> 5;

    // r2 per token, XLA row-reduce order (stride-32 ascending + shuffle tree)
    #pragma unroll 1
    for (int u = 0; u < 16; ++u) {
        int tok = wrp * 16 + u;
        const float* row = g_res + (size_t)(mBase + tok) * DC;
        float s = 0.f;
        #pragma unroll
        for (int j = 0; j < DC / 32; ++j) {
            float v = row[lane + j * 32];
            s = __fadd_rn(s, __fmul_rn(v, v));
        }
        #pragma unroll
        for (int off = 16; off; off >>= 1)
            s = __fadd_rn(s, __shfl_down_sync(0xffffffffu, s, off));
        if (lane == 0) r2s[tok] = s;
    }
    if (tid < 128) { best_val[tid] = FLT_MAX; best_idx[tid] = 0; }
    // ordering vs reads below guaranteed by syncthreads inside mma128

    #pragma unroll 1
    for (int nb = 0; nb < 8; ++nb) {
        float acc[8][8] = {};
        mma128<DC>(g_res + (size_t)mBase * DC,
                   cbt + (size_t)(nb * 128) * DC, DC, DC, acc, As, Bs);
        float4 e2a = *(const float4*)&g_e2[t * NBINS + nb * 128 + tx * 4];
        float4 e2b = *(const float4*)&g_e2[t * NBINS + nb * 128 + 64 + tx * 4];
        float e2r[8] = {e2a.x, e2a.y, e2a.z, e2a.w, e2b.x, e2b.y, e2b.z, e2b.w};
        #pragma unroll
        for (int i = 0; i < 8; ++i) {
            int tok = map8(ty * 4, i);
            float r2 = r2s[tok];
            float bv = FLT_MAX; int bi = 0;
            #pragma unroll
            for (int j = 0; j < 8; ++j) {
                // reference rounding: fl(fl(r2 - 2*dot) + e2); 2*dot is exact.
                float s = __fadd_rn(__fsub_rn(r2, __fmul_rn(2.0f, acc[i][j])), e2r[j]);
                int idx = nb * 128 + map8(tx * 4, j);
                if (s < bv || (s == bv && idx < bi)) { bv = s; bi = idx; }
            }
            // reduce across the 16 lanes covering this token's bins
            #pragma unroll
            for (int off = 8; off; off >>= 1) {
                float v2 = __shfl_down_sync(0xffffffffu, bv, off, 16);
                int   i2 = __shfl_down_sync(0xffffffffu, bi, off, 16);
                if (v2 < bv || (v2 == bv && i2 < bi)) { bv = v2; bi = i2; }
            }
            if (tx == 0) {   // unique (ty, tok) owner per warp-half: no race
                if (bv < best_val[tok] || (bv == best_val[tok] && bi < best_idx[tok])) {
                    best_val[tok] = bv; best_idx[tok] = bi;
                }
            }
        }
    }
    __syncthreads();

    // residual -= codebook[idx]; commit += ||new residual||^2 ; write idx
    const int tok = tid >> 1;            // 2 threads per token
    const int seg = tid & 1;             // 128 dims each
    const int m   = mBase + tok;
    const int bi  = best_idx[tok];
    const float4* e4 = (const float4*)(cbt + (size_t)bi * DC) + seg * 32;
    float4*       r4 = (float4*)(g_res + (size_t)m * DC) + seg * 32;
    float ss = 0.f;
    #pragma unroll
    for (int u = 0; u < 32; ++u) {
        float4 r = r4[u], e = e4[u];
        r.x = __fsub_rn(r.x, e.x); r.y = __fsub_rn(r.y, e.y);
        r.z = __fsub_rn(r.z, e.z); r.w = __fsub_rn(r.w, e.w);
        r4[u] = r;
        ss = fmaf(r.x, r.x, fmaf(r.y, r.y, fmaf(r.z, r.z, fmaf(r.w, r.w, ss))));
    }
    if (seg == 0) idx_out[m] = (float)bi;
    #pragma unroll
    for (int off = 16; off; off >>= 1) ss += __shfl_down_sync(0xffffffffu, ss, off);
    if (lane == 0) warp_sum[wrp] = ss;
    __syncthreads();
    if (tid == 0) {
        float s = 0.f;
        #pragma unroll
        for (int w = 0; w < 8; ++w) s += warp_sum[w];
        atomicAdd(&g_commit, s);
    }
}

// -------- quantized = h - residual_final (overwrite g_h) -------------------
__global__ void qsum_kernel() {
    size_t i = (size_t)blockIdx.x * blockDim.x + threadIdx.x;
    float4* h4 = (float4*)g_h;
    const float4* r4 = (const float4*)g_res;
    float4 h = h4[i], r = r4[i];
    h.x = __fsub_rn(h.x, r.x); h.y = __fsub_rn(h.y, r.y);
    h.z = __fsub_rn(h.z, r.z); h.w = __fsub_rn(h.w, r.w);
    h4[i] = h;
}

// -------- GEMM 2: out = quantized @ out_w^T + out_b ------------------------
__global__ void __launch_bounds__(256, 2) gemm_out_kernel(const float* __restrict__ w,
                                                          const float* __restrict__ b,
                                                          float* __restrict__ outp)
{
    __shared__ __align__(16) float As[16][132];
    __shared__ __align__(16) float Bs[16][132];
    const int mBase = blockIdx.y * 128;
    const int nBase = blockIdx.x * 128;
    float acc[8][8] = {};
    mma128<DC>(g_h + (size_t)mBase * DC, w + (size_t)nBase * DC, DC, DC, acc, As, Bs);
    const int tx = threadIdx.x & 15, ty = threadIdx.x >> 4;
    #pragma unroll
    for (int i = 0; i < 8; ++i) {
        int m = mBase + map8(ty * 4, i);
        #pragma unroll
        for (int j = 0; j < 8; ++j) {
            int n = nBase + map8(tx * 4, j);
            outp[(size_t)m * DIN + n] = __fadd_rn(acc[i][j], b[n]);
        }
    }
}

__global__ void fin_kernel(float* __restrict__ loss) {
    // commit_loss = 0.1 * sum_t mean(r_new_t^2);  mean denom = 8*4096*256
    *loss = 0.1f * g_commit * (1.0f / 8388608.0f);
}

extern "C" void kernel_launch(void* const* d_in, const int* in_sizes, int n_in,
                              void* d_out, int out_size)
{
    const float* x     = (const float*)d_in[0];
    const float* in_w  = (const float*)d_in[1];
    const float* in_b  = (const float*)d_in[2];
    const float* out_w = (const float*)d_in[3];
    const float* out_b = (const float*)d_in[4];
    const float* cb    = (const float*)d_in[5];

    float* outp     = (float*)d_out;                       // [32768, 512]
    float* idx_out  = outp + (size_t)N_TOK * DIN;          // [8, 32768]
    float* loss_out = outp + (size_t)out_size - 1;         // scalar

    init_kernel<<<1, 1>>>();
    e2_kernel<<<(NQCB * NBINS * 32) / 256, 256>>>(cb);
    gemm_in_kernel<<<dim3(DC / 128, N_TOK / 128), 256>>>(x, in_w, in_b);
    for (int t = 0; t < NQCB; ++t)
        quant_kernel<<<N_TOK / 128, 256>>>(cb + (size_t)t * NBINS * DC, t,
                                           idx_out + (size_t)t * N_TOK);
    qsum_kernel<<<(N_TOK * DC / 4) / 256, 256>>>();
    gemm_out_kernel<<<dim3(DIN / 128, N_TOK / 128), 256>>>(out_w, out_b, outp);
    fin_kernel<<<1, 1>>>(loss_out);
}

// round 5
// speedup vs baseline: 1.2813x; 1.0540x over previous
#include <cuda_runtime.h>
#include <math.h>
#include <float.h>

#define N_TOK 32768   // B*T
#define DC    256
#define DIN   512
#define NQCB  8
#define NBINS 1024

// -------- scratch (device globals: allocation-free) --------
__device__ float g_h[(size_t)N_TOK * DC];     // tanh projection (later overwritten with quantized)
__device__ float g_res[(size_t)N_TOK * DC];   // running residual
__device__ float g_e2[NQCB * NBINS];          // per-bin squared norms (XLA reduce order)
__device__ float g_commit;                    // commit sum-of-squares accumulator

__global__ void init_kernel() { g_commit = 0.f; }

// XLA/Eigen float tanh rational approximation (bit-matching the reference's tanh)
__device__ __forceinline__ float tanh_ref(float x) {
    const float kClamp = 7.90531110763549805f;
    float xc = fminf(fmaxf(x, -kClamp), kClamp);
    const float a1  = 4.89352455891786e-03f, a3 = 6.37261928875436e-04f,
                a5  = 1.48572235717979e-05f, a7 = 5.12229709037114e-08f,
                a9  = -8.60467152213735e-11f, a11 = 2.00018790482477e-13f,
                a13 = -2.76076847742355e-16f;
    const float b0 = 4.89352518554385e-03f, b2 = 2.26843463243900e-03f,
                b4 = 1.18534705686654e-04f, b6 = 1.19825839466702e-06f;
    float x2 = __fmul_rn(xc, xc);
    float p = fmaf(x2, a13, a11);
    p = fmaf(x2, p, a9);
    p = fmaf(x2, p, a7);
    p = fmaf(x2, p, a5);
    p = fmaf(x2, p, a3);
    p = fmaf(x2, p, a1);
    p = __fmul_rn(xc, p);
    float q = fmaf(x2, b6, b4);
    q = fmaf(x2, q, b2);
    q = fmaf(x2, q, b0);
    float r = __fdiv_rn(p, q);
    return (fabsf(x) < 0.0004f) ? x : r;
}

// ||e||^2 per codebook row, XLA row-reduce order
__global__ void e2_kernel(const float* __restrict__ cb) {
    int gw   = (blockIdx.x * blockDim.x + threadIdx.x) >> 5;
    int lane = threadIdx.x & 31;
    if (gw >= NQCB * NBINS) return;
    const float* row = cb + (size_t)gw * DC;
    float s = 0.f;
    #pragma unroll
    for (int j = 0; j < DC / 32; ++j) {
        float v = row[lane + j * 32];
        s = __fadd_rn(s, __fmul_rn(v, v));
    }
    #pragma unroll
    for (int off = 16; off; off >>= 1)
        s = __fadd_rn(s, __shfl_down_sync(0xffffffffu, s, off));
    if (lane == 0) g_e2[gw] = s;
}

// ---------------------------------------------------------------------------
// 128x128 tile fp32 core, double-buffered smem, ONE barrier per 16-k chunk.
// 256 threads (16x16), 8x8 per-thread accumulators as 2x2 grid of 4x4 tiles.
// Strictly sequential-k single-accumulator per output (bit-stable argmin).
// Pattern per chunk: LDG next -> FMA current buf -> STS next buf -> sync.
// ---------------------------------------------------------------------------
template<int KTOT>
__device__ __forceinline__ void mma128(const float* __restrict__ A,
                                       const float* __restrict__ B,
                                       int lda, int ldb,
                                       float (&acc)[8][8],
                                       float (*As)[16][132], float (*Bs)[16][132])
{
    const int tid = threadIdx.x;
    const int row = tid >> 1;          // 0..127
    const int kq  = (tid & 1) * 8;     // 0 or 8
    const int tx  = tid & 15;
    const int ty  = tid >> 4;
    constexpr int NC = KTOT / 16;

    // preload chunk 0 into buffer 0
    float4 pa0 = *(const float4*)(A + (size_t)row * lda + kq);
    float4 pa1 = *(const float4*)(A + (size_t)row * lda + kq + 4);
    float4 pb0 = *(const float4*)(B + (size_t)row * ldb + kq);
    float4 pb1 = *(const float4*)(B + (size_t)row * ldb + kq + 4);
    __syncthreads();   // caller's previous smem use (or prior call) complete
    As[0][kq + 0][row] = pa0.x; As[0][kq + 1][row] = pa0.y; As[0][kq + 2][row] = pa0.z; As[0][kq + 3][row] = pa0.w;
    As[0][kq + 4][row] = pa1.x; As[0][kq + 5][row] = pa1.y; As[0][kq + 6][row] = pa1.z; As[0][kq + 7][row] = pa1.w;
    Bs[0][kq + 0][row] = pb0.x; Bs[0][kq + 1][row] = pb0.y; Bs[0][kq + 2][row] = pb0.z; Bs[0][kq + 3][row] = pb0.w;
    Bs[0][kq + 4][row] = pb1.x; Bs[0][kq + 5][row] = pb1.y; Bs[0][kq + 6][row] = pb1.z; Bs[0][kq + 7][row] = pb1.w;
    __syncthreads();

    #pragma unroll 2
    for (int c = 0; c < NC; ++c) {
        const int cur = c & 1, nxt = cur ^ 1;
        if (c + 1 < NC) {
            const float* Ai = A + (size_t)row * lda + (c + 1) * 16 + kq;
            const float* Bi = B + (size_t)row * ldb + (c + 1) * 16 + kq;
            pa0 = *(const float4*)Ai;       pa1 = *(const float4*)(Ai + 4);
            pb0 = *(const float4*)Bi;       pb1 = *(const float4*)(Bi + 4);
        }
        #pragma unroll
        for (int k = 0; k < 16; ++k) {
            float4 a0 = *(const float4*)&As[cur][k][ty * 4];
            float4 a1 = *(const float4*)&As[cur][k][64 + ty * 4];
            float4 b0 = *(const float4*)&Bs[cur][k][tx * 4];
            float4 b1 = *(const float4*)&Bs[cur][k][64 + tx * 4];
            float ar[8] = {a0.x, a0.y, a0.z, a0.w, a1.x, a1.y, a1.z, a1.w};
            float br[8] = {b0.x, b0.y, b0.z, b0.w, b1.x, b1.y, b1.z, b1.w};
            #pragma unroll
            for (int i = 0; i < 8; ++i)
                #pragma unroll
                for (int j = 0; j < 8; ++j)
                    acc[i][j] = fmaf(ar[i], br[j], acc[i][j]);
        }
        if (c + 1 < NC) {
            As[nxt][kq + 0][row] = pa0.x; As[nxt][kq + 1][row] = pa0.y; As[nxt][kq + 2][row] = pa0.z; As[nxt][kq + 3][row] = pa0.w;
            As[nxt][kq + 4][row] = pa1.x; As[nxt][kq + 5][row] = pa1.y; As[nxt][kq + 6][row] = pa1.z; As[nxt][kq + 7][row] = pa1.w;
            Bs[nxt][kq + 0][row] = pb0.x; Bs[nxt][kq + 1][row] = pb0.y; Bs[nxt][kq + 2][row] = pb0.z; Bs[nxt][kq + 3][row] = pb0.w;
            Bs[nxt][kq + 4][row] = pb1.x; Bs[nxt][kq + 5][row] = pb1.y; Bs[nxt][kq + 6][row] = pb1.z; Bs[nxt][kq + 7][row] = pb1.w;
        }
        __syncthreads();
    }
}

// row/col mapping for the 2x2-of-4x4 layout
__device__ __forceinline__ int map8(int base4, int i) {   // i 0..7
    return (i < 4) ? base4 + i : 64 + base4 + (i - 4);
}

// -------- GEMM 1: h = tanh_ref(x @ in_w^T + in_b), writes g_h and g_res ----
__global__ void __launch_bounds__(256, 2) gemm_in_kernel(const float* __restrict__ x,
                                                         const float* __restrict__ w,
                                                         const float* __restrict__ b)
{
    __shared__ __align__(16) float As[2][16][132];
    __shared__ __align__(16) float Bs[2][16][132];
    const int mBase = blockIdx.y * 128;
    const int nBase = blockIdx.x * 128;
    float acc[8][8] = {};
    mma128<DIN>(x + (size_t)mBase * DIN, w + (size_t)nBase * DIN, DIN, DIN, acc, As, Bs);
    const int tx = threadIdx.x & 15, ty = threadIdx.x >> 4;
    #pragma unroll
    for (int i = 0; i < 8; ++i) {
        int m = mBase + map8(ty * 4, i);
        #pragma unroll
        for (int j = 0; j < 8; ++j) {
            int n = nBase + map8(tx * 4, j);
            float v = tanh_ref(__fadd_rn(acc[i][j], b[n]));   // CODEC_RANGE == 1.0
            g_h  [(size_t)m * DC + n] = v;
            g_res[(size_t)m * DC + n] = v;
        }
    }
}

// -------- per-step: r2 + distances (reference rounding) + argmin +
//          residual update + commit. One block = 128 tokens, all 1024 bins. --
__global__ void __launch_bounds__(256, 2) quant_kernel(const float* __restrict__ cbt,
                                                       int t, float* __restrict__ idx_out)
{
    __shared__ __align__(16) float As[2][16][132];
    __shared__ __align__(16) float Bs[2][16][132];
    __shared__ float r2s[128];
    __shared__ float best_val[128];
    __shared__ int   best_idx[128];
    __shared__ float warp_sum[8];
    const int tid   = threadIdx.x;
    const int mBase = blockIdx.x * 128;
    const int tx = tid & 15, ty = tid >> 4;
    const int lane = tid & 31, wrp = tid >> 5;

    // r2 per token, XLA row-reduce order (stride-32 ascending + shuffle tree)
    #pragma unroll 1
    for (int u = 0; u < 16; ++u) {
        int tok = wrp * 16 + u;
        const float* row = g_res + (size_t)(mBase + tok) * DC;
        float s = 0.f;
        #pragma unroll
        for (int j = 0; j < DC / 32; ++j) {
            float v = row[lane + j * 32];
            s = __fadd_rn(s, __fmul_rn(v, v));
        }
        #pragma unroll
        for (int off = 16; off; off >>= 1)
            s = __fadd_rn(s, __shfl_down_sync(0xffffffffu, s, off));
        if (lane == 0) r2s[tok] = s;
    }
    if (tid < 128) { best_val[tid] = FLT_MAX; best_idx[tid] = 0; }
    // ordering vs reads below guaranteed by syncthreads inside mma128

    #pragma unroll 1
    for (int nb = 0; nb < 8; ++nb) {
        float acc[8][8] = {};
        mma128<DC>(g_res + (size_t)mBase * DC,
                   cbt + (size_t)(nb * 128) * DC, DC, DC, acc, As, Bs);
        float4 e2a = *(const float4*)&g_e2[t * NBINS + nb * 128 + tx * 4];
        float4 e2b = *(const float4*)&g_e2[t * NBINS + nb * 128 + 64 + tx * 4];
        float e2r[8] = {e2a.x, e2a.y, e2a.z, e2a.w, e2b.x, e2b.y, e2b.z, e2b.w};
        #pragma unroll
        for (int i = 0; i < 8; ++i) {
            int tok = map8(ty * 4, i);
            float r2 = r2s[tok];
            float bv = FLT_MAX; int bi = 0;
            #pragma unroll
            for (int j = 0; j < 8; ++j) {
                // reference rounding: fl(fl(r2 - 2*dot) + e2); 2*dot is exact.
                float s = __fadd_rn(__fsub_rn(r2, __fmul_rn(2.0f, acc[i][j])), e2r[j]);
                int idx = nb * 128 + map8(tx * 4, j);
                if (s < bv || (s == bv && idx < bi)) { bv = s; bi = idx; }
            }
            // reduce across the 16 lanes covering this token's bins
            #pragma unroll
            for (int off = 8; off; off >>= 1) {
                float v2 = __shfl_down_sync(0xffffffffu, bv, off, 16);
                int   i2 = __shfl_down_sync(0xffffffffu, bi, off, 16);
                if (v2 < bv || (v2 == bv && i2 < bi)) { bv = v2; bi = i2; }
            }
            if (tx == 0) {   // unique (ty, tok) owner per warp-half: no race
                if (bv < best_val[tok] || (bv == best_val[tok] && bi < best_idx[tok])) {
                    best_val[tok] = bv; best_idx[tok] = bi;
                }
            }
        }
    }
    __syncthreads();

    // residual -= codebook[idx]; commit += ||new residual||^2 ; write idx
    const int tok = tid >> 1;            // 2 threads per token
    const int seg = tid & 1;             // 128 dims each
    const int m   = mBase + tok;
    const int bi  = best_idx[tok];
    const float4* e4 = (const float4*)(cbt + (size_t)bi * DC) + seg * 32;
    float4*       r4 = (float4*)(g_res + (size_t)m * DC) + seg * 32;
    float ss = 0.f;
    #pragma unroll
    for (int u = 0; u < 32; ++u) {
        float4 r = r4[u], e = e4[u];
        r.x = __fsub_rn(r.x, e.x); r.y = __fsub_rn(r.y, e.y);
        r.z = __fsub_rn(r.z, e.z); r.w = __fsub_rn(r.w, e.w);
        r4[u] = r;
        ss = fmaf(r.x, r.x, fmaf(r.y, r.y, fmaf(r.z, r.z, fmaf(r.w, r.w, ss))));
    }
    if (seg == 0) idx_out[m] = (float)bi;
    #pragma unroll
    for (int off = 16; off; off >>= 1) ss += __shfl_down_sync(0xffffffffu, ss, off);
    if (lane == 0) warp_sum[wrp] = ss;
    __syncthreads();
    if (tid == 0) {
        float s = 0.f;
        #pragma unroll
        for (int w = 0; w < 8; ++w) s += warp_sum[w];
        atomicAdd(&g_commit, s);
    }
}

// -------- quantized = h - residual_final (overwrite g_h) -------------------
__global__ void qsum_kernel() {
    size_t i = (size_t)blockIdx.x * blockDim.x + threadIdx.x;
    float4* h4 = (float4*)g_h;
    const float4* r4 = (const float4*)g_res;
    float4 h = h4[i], r = r4[i];
    h.x = __fsub_rn(h.x, r.x); h.y = __fsub_rn(h.y, r.y);
    h.z = __fsub_rn(h.z, r.z); h.w = __fsub_rn(h.w, r.w);
    h4[i] = h;
}

// -------- GEMM 2: out = quantized @ out_w^T + out_b ------------------------
__global__ void __launch_bounds__(256, 2) gemm_out_kernel(const float* __restrict__ w,
                                                          const float* __restrict__ b,
                                                          float* __restrict__ outp)
{
    __shared__ __align__(16) float As[2][16][132];
    __shared__ __align__(16) float Bs[2][16][132];
    const int mBase = blockIdx.y * 128;
    const int nBase = blockIdx.x * 128;
    float acc[8][8] = {};
    mma128<DC>(g_h + (size_t)mBase * DC, w + (size_t)nBase * DC, DC, DC, acc, As, Bs);
    const int tx = threadIdx.x & 15, ty = threadIdx.x >> 4;
    #pragma unroll
    for (int i = 0; i < 8; ++i) {
        int m = mBase + map8(ty * 4, i);
        #pragma unroll
        for (int j = 0; j < 8; ++j) {
            int n = nBase + map8(tx * 4, j);
            outp[(size_t)m * DIN + n] = __fadd_rn(acc[i][j], b[n]);
        }
    }
}

__global__ void fin_kernel(float* __restrict__ loss) {
    // commit_loss = 0.1 * sum_t mean(r_new_t^2);  mean denom = 8*4096*256
    *loss = 0.1f * g_commit * (1.0f / 8388608.0f);
}

extern "C" void kernel_launch(void* const* d_in, const int* in_sizes, int n_in,
                              void* d_out, int out_size)
{
    const float* x     = (const float*)d_in[0];
    const float* in_w  = (const float*)d_in[1];
    const float* in_b  = (const float*)d_in[2];
    const float* out_w = (const float*)d_in[3];
    const float* out_b = (const float*)d_in[4];
    const float* cb    = (const float*)d_in[5];

    float* outp     = (float*)d_out;                       // [32768, 512]
    float* idx_out  = outp + (size_t)N_TOK * DIN;          // [8, 32768]
    float* loss_out = outp + (size_t)out_size - 1;         // scalar

    init_kernel<<<1, 1>>>();
    e2_kernel<<<(NQCB * NBINS * 32) / 256, 256>>>(cb);
    gemm_in_kernel<<<dim3(DC / 128, N_TOK / 128), 256>>>(x, in_w, in_b);
    for (int t = 0; t < NQCB; ++t)
        quant_kernel<<<N_TOK / 128, 256>>>(cb + (size_t)t * NBINS * DC, t,
                                           idx_out + (size_t)t * N_TOK);
    qsum_kernel<<<(N_TOK * DC / 4) / 256, 256>>>();
    gemm_out_kernel<<<dim3(DIN / 128, N_TOK / 128), 256>>>(out_w, out_b, outp);
    fin_kernel<<<1, 1>>>(loss_out);
}

// round 7
// speedup vs baseline: 2.0014x; 1.5620x over previous
#include <cuda_runtime.h>
#include <cuda_bf16.h>
#include <cuda_fp16.h>
#include <math.h>
#include <float.h>

#define N_TOK 32768   // B*T
#define DC    256
#define DIN   512
#define NQCB  8
#define NBINS 1024
#define TAU   6.0f    // screen window (bf16 mma + fp16 storage error budget)

// -------- scratch (device globals: allocation-free) --------
__device__ float g_h[(size_t)N_TOK * DC];            // tanh projection (later quantized)
__device__ float g_res[(size_t)N_TOK * DC];          // running residual fp32
__device__ __nv_bfloat16 g_res16[(size_t)N_TOK * DC];        // residual bf16 (screen A)
__device__ __nv_bfloat16 g_cb16[(size_t)NQCB * NBINS * DC];  // codebooks bf16 (screen B)
__device__ __half g_S[(size_t)N_TOK * NBINS];        // approx screen scores
__device__ float g_r2[N_TOK];                        // ||r||^2 per token (XLA order)
__device__ float g_e2[NQCB * NBINS];                 // per-bin squared norms (XLA order)
__device__ float g_commit;

__global__ void init_kernel() { g_commit = 0.f; }

// XLA/Eigen float tanh rational approximation (matches reference bits)
__device__ __forceinline__ float tanh_ref(float x) {
    const float kClamp = 7.90531110763549805f;
    float xc = fminf(fmaxf(x, -kClamp), kClamp);
    const float a1  = 4.89352455891786e-03f, a3 = 6.37261928875436e-04f,
                a5  = 1.48572235717979e-05f, a7 = 5.12229709037114e-08f,
                a9  = -8.60467152213735e-11f, a11 = 2.00018790482477e-13f,
                a13 = -2.76076847742355e-16f;
    const float b0 = 4.89352518554385e-03f, b2 = 2.26843463243900e-03f,
                b4 = 1.18534705686654e-04f, b6 = 1.19825839466702e-06f;
    float x2 = __fmul_rn(xc, xc);
    float p = fmaf(x2, a13, a11);
    p = fmaf(x2, p, a9);  p = fmaf(x2, p, a7);
    p = fmaf(x2, p, a5);  p = fmaf(x2, p, a3);
    p = fmaf(x2, p, a1);  p = __fmul_rn(xc, p);
    float q = fmaf(x2, b6, b4);
    q = fmaf(x2, q, b2);  q = fmaf(x2, q, b0);
    float r = __fdiv_rn(p, q);
    return (fabsf(x) < 0.0004f) ? x : r;
}

// ||e||^2 per codebook row, XLA row-reduce order
__global__ void e2_kernel(const float* __restrict__ cb) {
    int gw   = (blockIdx.x * blockDim.x + threadIdx.x) >> 5;
    int lane = threadIdx.x & 31;
    if (gw >= NQCB * NBINS) return;
    const float* row = cb + (size_t)gw * DC;
    float s = 0.f;
    #pragma unroll
    for (int j = 0; j < DC / 32; ++j) {
        float v = row[lane + j * 32];
        s = __fadd_rn(s, __fmul_rn(v, v));
    }
    #pragma unroll
    for (int off = 16; off; off >>= 1)
        s = __fadd_rn(s, __shfl_down_sync(0xffffffffu, s, off));
    if (lane == 0) g_e2[gw] = s;
}

// codebooks fp32 -> bf16
__global__ void cb16_kernel(const float* __restrict__ cb) {
    size_t i = (size_t)blockIdx.x * blockDim.x + threadIdx.x;   // float4 index
    float4 v = ((const float4*)cb)[i];
    __nv_bfloat16 o[4];
    o[0] = __float2bfloat16(v.x); o[1] = __float2bfloat16(v.y);
    o[2] = __float2bfloat16(v.z); o[3] = __float2bfloat16(v.w);
    *(uint2*)(g_cb16 + i * 4) = *(uint2*)o;
}

// after gemm_in: residual bf16 + r2 (one warp per token)
__global__ void prep_kernel() {
    const int wid = threadIdx.x >> 5, lane = threadIdx.x & 31;
    const int tok = blockIdx.x * 8 + wid;
    const float* r = g_res + (size_t)tok * DC;
    __nv_bfloat16* r16 = g_res16 + (size_t)tok * DC;
    float s = 0.f;
    #pragma unroll
    for (int j = 0; j < 8; ++j) {
        int d = lane + j * 32;
        float v = r[d];
        r16[d] = __float2bfloat16(v);
        s = __fadd_rn(s, __fmul_rn(v, v));
    }
    #pragma unroll
    for (int off = 16; off; off >>= 1)
        s = __fadd_rn(s, __shfl_down_sync(0xffffffffu, s, off));
    if (lane == 0) g_r2[tok] = s;
}

// ---------------- PTX helpers ----------------
__device__ __forceinline__ unsigned int smaddr(const void* p) {
    return (unsigned int)__cvta_generic_to_shared(p);
}
__device__ __forceinline__ void cp16(unsigned int dst, const void* src) {
    asm volatile("cp.async.cg.shared.global [%0], [%1], 16;\n" :: "r"(dst), "l"(src));
}
__device__ __forceinline__ void cp_commit() { asm volatile("cp.async.commit_group;\n"); }
__device__ __forceinline__ void cp_wait0()  { asm volatile("cp.async.wait_group 0;\n"); }
__device__ __forceinline__ void ldmx4(unsigned int& r0, unsigned int& r1,
                                      unsigned int& r2, unsigned int& r3,
                                      unsigned int addr) {
    asm volatile("ldmatrix.sync.aligned.m8n8.x4.shared.b16 {%0,%1,%2,%3}, [%4];\n"
                 : "=r"(r0), "=r"(r1), "=r"(r2), "=r"(r3) : "r"(addr));
}
__device__ __forceinline__ void mma16816(float* d, const unsigned int* a,
                                         unsigned int b0, unsigned int b1) {
    asm volatile("mma.sync.aligned.m16n8k16.row.col.f32.bf16.bf16.f32 "
                 "{%0,%1,%2,%3}, {%4,%5,%6,%7}, {%8,%9}, {%0,%1,%2,%3};\n"
                 : "+f"(d[0]), "+f"(d[1]), "+f"(d[2]), "+f"(d[3])
                 : "r"(a[0]), "r"(a[1]), "r"(a[2]), "r"(a[3]), "r"(b0), "r"(b1));
}

// ---------------------------------------------------------------------------
// SCREEN: S[m][n] = e2[n] - 2 * (bf16(r_m) . bf16(e_n)), fp16 output.
// Block tile 128(M)x128(N), k-chunk 32, 256 thr = 8 warps (4 M x 2 N),
// warp tile 32x64 via mma.sync m16n8k16 bf16. Rows padded to 40 halfs (80B).
// ---------------------------------------------------------------------------
__global__ void __launch_bounds__(256) screen_kernel(int t)
{
    __shared__ __align__(16) unsigned short smA[2][128 * 40];
    __shared__ __align__(16) unsigned short smB[2][128 * 40];
    const int tid   = threadIdx.x;
    const int mBase = blockIdx.y * 128;
    const int nBase = blockIdx.x * 128;
    const int wid = tid >> 5, lane = tid & 31;
    const int wm = wid & 3, wn = wid >> 2;

    const int c0 = tid * 2;
    const int row0 = c0 >> 2, q0 = c0 & 3;
    const int row1 = (c0 + 1) >> 2, q1 = (c0 + 1) & 3;
    const __nv_bfloat16* Ag = g_res16 + (size_t)mBase * DC;
    const __nv_bfloat16* Bg = g_cb16 + (size_t)t * NBINS * DC + (size_t)nBase * DC;
    const float* e2t = g_e2 + t * NBINS;

    float acc[2][8][4];
    #pragma unroll
    for (int i = 0; i < 2; ++i)
        #pragma unroll
        for (int j = 0; j < 8; ++j)
            #pragma unroll
            for (int k = 0; k < 4; ++k) acc[i][j][k] = 0.f;

    // prologue: chunk 0 -> buffer 0
    cp16(smaddr(&smA[0][row0 * 40 + q0 * 8]), Ag + row0 * DC + q0 * 8);
    cp16(smaddr(&smA[0][row1 * 40 + q1 * 8]), Ag + row1 * DC + q1 * 8);
    cp16(smaddr(&smB[0][row0 * 40 + q0 * 8]), Bg + row0 * DC + q0 * 8);
    cp16(smaddr(&smB[0][row1 * 40 + q1 * 8]), Bg + row1 * DC + q1 * 8);
    cp_commit(); cp_wait0(); __syncthreads();

    #pragma unroll 1
    for (int kt = 0; kt < DC / 32; ++kt) {
        const int cur = kt & 1, nxt = cur ^ 1;
        if (kt + 1 < DC / 32) {
            const int ko = (kt + 1) * 32;
            cp16(smaddr(&smA[nxt][row0 * 40 + q0 * 8]), Ag + row0 * DC + ko + q0 * 8);
            cp16(smaddr(&smA[nxt][row1 * 40 + q1 * 8]), Ag + row1 * DC + ko + q1 * 8);
            cp16(smaddr(&smB[nxt][row0 * 40 + q0 * 8]), Bg + row0 * DC + ko + q0 * 8);
            cp16(smaddr(&smB[nxt][row1 * 40 + q1 * 8]), Bg + row1 * DC + ko + q1 * 8);
            cp_commit();
        }
        #pragma unroll
        for (int c16 = 0; c16 < 2; ++c16) {
            unsigned int a[2][4];
            #pragma unroll
            for (int i = 0; i < 2; ++i) {
                int r   = wm * 32 + i * 16 + ((lane >> 3) & 1) * 8 + (lane & 7);
                int col = c16 * 16 + ((lane >> 4) & 1) * 8;
                ldmx4(a[i][0], a[i][1], a[i][2], a[i][3],
                      smaddr(&smA[cur][r * 40 + col]));
            }
            #pragma unroll
            for (int jg = 0; jg < 4; ++jg) {
                unsigned int b0, b1, b2, b3;
                int g  = lane >> 3;
                int rB = wn * 64 + jg * 16 + (g >> 1) * 8 + (lane & 7);
                int cB = c16 * 16 + (g & 1) * 8;
                ldmx4(b0, b1, b2, b3, smaddr(&smB[cur][rB * 40 + cB]));
                mma16816(acc[0][jg * 2],     a[0], b0, b1);
                mma16816(acc[1][jg * 2],     a[1], b0, b1);
                mma16816(acc[0][jg * 2 + 1], a[0], b2, b3);
                mma16816(acc[1][jg * 2 + 1], a[1], b2, b3);
            }
        }
        cp_wait0(); __syncthreads();
    }

    // epilogue: s = e2 - 2*dot, fp16 store
    #pragma unroll
    for (int i = 0; i < 2; ++i) {
        #pragma unroll
        for (int j = 0; j < 8; ++j) {
            int n  = nBase + wn * 64 + j * 8 + (lane & 3) * 2;
            int m0 = mBase + wm * 32 + i * 16 + (lane >> 2);
            float e0 = e2t[n - nBase + nBase], e1 = e2t[n + 1 - nBase + nBase];
            __half2 lo = __floats2half2_rn(fmaf(-2.f, acc[i][j][0], e0),
                                           fmaf(-2.f, acc[i][j][1], e1));
            __half2 hi = __floats2half2_rn(fmaf(-2.f, acc[i][j][2], e0),
                                           fmaf(-2.f, acc[i][j][3], e1));
            *(__half2*)(g_S + (size_t)m0 * NBINS + n)       = lo;
            *(__half2*)(g_S + (size_t)(m0 + 8) * NBINS + n) = hi;
        }
    }
}

// ---------------------------------------------------------------------------
// RERANK: one warp per token: screen min, exact fp32 re-eval of bins within
// TAU (validated recipe), argmin (tie->lower), residual update fp32+bf16,
// next r2 (XLA order), block-reduced commit, idx.
// ---------------------------------------------------------------------------
__global__ void __launch_bounds__(256) rerank_kernel(const float* __restrict__ cbt,
                                                     int t, float* __restrict__ idx_out)
{
    __shared__ float wsum[8];
    const int wid = threadIdx.x >> 5, lane = threadIdx.x & 31;
    const int tok = blockIdx.x * 8 + wid;
    const __half* Srow = g_S + (size_t)tok * NBINS;
    const float* e2t = g_e2 + t * NBINS;

    int4 sv[4];
    #pragma unroll
    for (int j = 0; j < 4; ++j) sv[j] = ((const int4*)Srow)[j * 32 + lane];

    float mn = FLT_MAX;
    #pragma unroll
    for (int j = 0; j < 4; ++j) {
        const __half* h = (const __half*)&sv[j];
        #pragma unroll
        for (int i = 0; i < 8; ++i) mn = fminf(mn, __half2float(h[i]));
    }
    #pragma unroll
    for (int off = 16; off; off >>= 1)
        mn = fminf(mn, __shfl_xor_sync(0xffffffffu, mn, off));
    const float thr = mn + TAU;

    const float r2tok = g_r2[tok];
    const float* r = g_res + (size_t)tok * DC;
    float bestv = FLT_MAX; int besti = NBINS;
    #pragma unroll
    for (int j = 0; j < 4; ++j) {
        const __half* h = (const __half*)&sv[j];
        #pragma unroll
        for (int i = 0; i < 8; ++i) {
            if (__half2float(h[i]) <= thr) {
                int bin = j * 256 + lane * 8 + i;
                const float* e = cbt + (size_t)bin * DC;
                float acc = 0.f;
                #pragma unroll 8
                for (int k = 0; k < DC; ++k) acc = fmaf(r[k], e[k], acc);
                // reference rounding: fl(fl(r2 - 2*dot) + e2)
                float sc = __fadd_rn(__fsub_rn(r2tok, __fmul_rn(2.f, acc)), e2t[bin]);
                if (sc < bestv || (sc == bestv && bin < besti)) { bestv = sc; besti = bin; }
            }
        }
    }
    #pragma unroll
    for (int off = 16; off; off >>= 1) {
        float v = __shfl_xor_sync(0xffffffffu, bestv, off);
        int   i = __shfl_xor_sync(0xffffffffu, besti, off);
        if (v < bestv || (v == bestv && i < besti)) { bestv = v; besti = i; }
    }

    // update residual (fp32 + bf16), next r2 (XLA order), commit, idx
    const float* e = cbt + (size_t)besti * DC;
    float* rw = g_res + (size_t)tok * DC;
    __nv_bfloat16* rw16 = g_res16 + (size_t)tok * DC;
    float s = 0.f;
    #pragma unroll
    for (int j = 0; j < 8; ++j) {
        int d = lane + j * 32;
        float rn_ = __fsub_rn(rw[d], e[d]);
        rw[d] = rn_;
        rw16[d] = __float2bfloat16(rn_);
        s = __fadd_rn(s, __fmul_rn(rn_, rn_));
    }
    #pragma unroll
    for (int off = 16; off; off >>= 1)
        s = __fadd_rn(s, __shfl_down_sync(0xffffffffu, s, off));
    if (lane == 0) {
        g_r2[tok] = s;
        wsum[wid] = s;
        idx_out[tok] = (float)besti;
    }
    __syncthreads();
    if (threadIdx.x == 0) {
        float acc = 0.f;
        #pragma unroll
        for (int w = 0; w < 8; ++w) acc += wsum[w];
        atomicAdd(&g_commit, acc);
    }
}

// ---------------------------------------------------------------------------
// fp32 SIMT GEMM core (unchanged, passing) for in/out projections
// ---------------------------------------------------------------------------
template<int KTOT>
__device__ __forceinline__ void mma128(const float* __restrict__ A,
                                       const float* __restrict__ B,
                                       int lda, int ldb,
                                       float (&acc)[8][8],
                                       float (*As)[16][132], float (*Bs)[16][132])
{
    const int tid = threadIdx.x;
    const int row = tid >> 1;
    const int kq  = (tid & 1) * 8;
    const int tx  = tid & 15;
    const int ty  = tid >> 4;
    const int NC = KTOT / 16;

    float4 pa0 = *(const float4*)(A + (size_t)row * lda + kq);
    float4 pa1 = *(const float4*)(A + (size_t)row * lda + kq + 4);
    float4 pb0 = *(const float4*)(B + (size_t)row * ldb + kq);
    float4 pb1 = *(const float4*)(B + (size_t)row * ldb + kq + 4);
    __syncthreads();
    As[0][kq + 0][row] = pa0.x; As[0][kq + 1][row] = pa0.y; As[0][kq + 2][row] = pa0.z; As[0][kq + 3][row] = pa0.w;
    As[0][kq + 4][row] = pa1.x; As[0][kq + 5][row] = pa1.y; As[0][kq + 6][row] = pa1.z; As[0][kq + 7][row] = pa1.w;
    Bs[0][kq + 0][row] = pb0.x; Bs[0][kq + 1][row] = pb0.y; Bs[0][kq + 2][row] = pb0.z; Bs[0][kq + 3][row] = pb0.w;
    Bs[0][kq + 4][row] = pb1.x; Bs[0][kq + 5][row] = pb1.y; Bs[0][kq + 6][row] = pb1.z; Bs[0][kq + 7][row] = pb1.w;
    __syncthreads();

    #pragma unroll 2
    for (int c = 0; c < NC; ++c) {
        const int cur = c & 1, nxt = cur ^ 1;
        if (c + 1 < NC) {
            const float* Ai = A + (size_t)row * lda + (c + 1) * 16 + kq;
            const float* Bi = B + (size_t)row * ldb + (c + 1) * 16 + kq;
            pa0 = *(const float4*)Ai;  pa1 = *(const float4*)(Ai + 4);
            pb0 = *(const float4*)Bi;  pb1 = *(const float4*)(Bi + 4);
        }
        #pragma unroll
        for (int k = 0; k < 16; ++k) {
            float4 a0 = *(const float4*)&As[cur][k][ty * 4];
            float4 a1 = *(const float4*)&As[cur][k][64 + ty * 4];
            float4 b0 = *(const float4*)&Bs[cur][k][tx * 4];
            float4 b1 = *(const float4*)&Bs[cur][k][64 + tx * 4];
            float ar[8] = {a0.x, a0.y, a0.z, a0.w, a1.x, a1.y, a1.z, a1.w};
            float br[8] = {b0.x, b0.y, b0.z, b0.w, b1.x, b1.y, b1.z, b1.w};
            #pragma unroll
            for (int i = 0; i < 8; ++i)
                #pragma unroll
                for (int j = 0; j < 8; ++j)
                    acc[i][j] = fmaf(ar[i], br[j], acc[i][j]);
        }
        if (c + 1 < NC) {
            As[nxt][kq + 0][row] = pa0.x; As[nxt][kq + 1][row] = pa0.y; As[nxt][kq + 2][row] = pa0.z; As[nxt][kq + 3][row] = pa0.w;
            As[nxt][kq + 4][row] = pa1.x; As[nxt][kq + 5][row] = pa1.y; As[nxt][kq + 6][row] = pa1.z; As[nxt][kq + 7][row] = pa1.w;
            Bs[nxt][kq + 0][row] = pb0.x; Bs[nxt][kq + 1][row] = pb0.y; Bs[nxt][kq + 2][row] = pb0.z; Bs[nxt][kq + 3][row] = pb0.w;
            Bs[nxt][kq + 4][row] = pb1.x; Bs[nxt][kq + 5][row] = pb1.y; Bs[nxt][kq + 6][row] = pb1.z; Bs[nxt][kq + 7][row] = pb1.w;
        }
        __syncthreads();
    }
}

__device__ __forceinline__ int map8(int base4, int i) {
    return (i < 4) ? base4 + i : 64 + base4 + (i - 4);
}

__global__ void __launch_bounds__(256, 2) gemm_in_kernel(const float* __restrict__ x,
                                                         const float* __restrict__ w,
                                                         const float* __restrict__ b)
{
    __shared__ __align__(16) float As[2][16][132];
    __shared__ __align__(16) float Bs[2][16][132];
    const int mBase = blockIdx.y * 128;
    const int nBase = blockIdx.x * 128;
    float acc[8][8] = {};
    mma128<DIN>(x + (size_t)mBase * DIN, w + (size_t)nBase * DIN, DIN, DIN, acc, As, Bs);
    const int tx = threadIdx.x & 15, ty = threadIdx.x >> 4;
    #pragma unroll
    for (int i = 0; i < 8; ++i) {
        int m = mBase + map8(ty * 4, i);
        #pragma unroll
        for (int j = 0; j < 8; ++j) {
            int n = nBase + map8(tx * 4, j);
            float v = tanh_ref(__fadd_rn(acc[i][j], b[n]));
            g_h  [(size_t)m * DC + n] = v;
            g_res[(size_t)m * DC + n] = v;
        }
    }
}

__global__ void qsum_kernel() {
    size_t i = (size_t)blockIdx.x * blockDim.x + threadIdx.x;
    float4* h4 = (float4*)g_h;
    const float4* r4 = (const float4*)g_res;
    float4 h = h4[i], r = r4[i];
    h.x = __fsub_rn(h.x, r.x); h.y = __fsub_rn(h.y, r.y);
    h.z = __fsub_rn(h.z, r.z); h.w = __fsub_rn(h.w, r.w);
    h4[i] = h;
}

__global__ void __launch_bounds__(256, 2) gemm_out_kernel(const float* __restrict__ w,
                                                          const float* __restrict__ b,
                                                          float* __restrict__ outp)
{
    __shared__ __align__(16) float As[2][16][132];
    __shared__ __align__(16) float Bs[2][16][132];
    const int mBase = blockIdx.y * 128;
    const int nBase = blockIdx.x * 128;
    float acc[8][8] = {};
    mma128<DC>(g_h + (size_t)mBase * DC, w + (size_t)nBase * DC, DC, DC, acc, As, Bs);
    const int tx = threadIdx.x & 15, ty = threadIdx.x >> 4;
    #pragma unroll
    for (int i = 0; i < 8; ++i) {
        int m = mBase + map8(ty * 4, i);
        #pragma unroll
        for (int j = 0; j < 8; ++j) {
            int n = nBase + map8(tx * 4, j);
            outp[(size_t)m * DIN + n] = __fadd_rn(acc[i][j], b[n]);
        }
    }
}

__global__ void fin_kernel(float* __restrict__ loss) {
    *loss = 0.1f * g_commit * (1.0f / 8388608.0f);
}

extern "C" void kernel_launch(void* const* d_in, const int* in_sizes, int n_in,
                              void* d_out, int out_size)
{
    const float* x     = (const float*)d_in[0];
    const float* in_w  = (const float*)d_in[1];
    const float* in_b  = (const float*)d_in[2];
    const float* out_w = (const float*)d_in[3];
    const float* out_b = (const float*)d_in[4];
    const float* cb    = (const float*)d_in[5];

    float* outp     = (float*)d_out;                       // [32768, 512]
    float* idx_out  = outp + (size_t)N_TOK * DIN;          // [8, 32768]
    float* loss_out = outp + (size_t)out_size - 1;         // scalar

    init_kernel<<<1, 1>>>();
    e2_kernel<<<(NQCB * NBINS * 32) / 256, 256>>>(cb);
    cb16_kernel<<<(NQCB * NBINS * DC / 4) / 256, 256>>>(cb);
    gemm_in_kernel<<<dim3(DC / 128, N_TOK / 128), 256>>>(x, in_w, in_b);
    prep_kernel<<<N_TOK / 8, 256>>>();
    for (int t = 0; t < NQCB; ++t) {
        screen_kernel<<<dim3(NBINS / 128, N_TOK / 128), 256>>>(t);
        rerank_kernel<<<N_TOK / 8, 256>>>(cb + (size_t)t * NBINS * DC, t,
                                          idx_out + (size_t)t * N_TOK);
    }
    qsum_kernel<<<(N_TOK * DC / 4) / 256, 256>>>();
    gemm_out_kernel<<<dim3(DIN / 128, N_TOK / 128), 256>>>(out_w, out_b, outp);
    fin_kernel<<<1, 1>>>(loss_out);
}